// round 1
// baseline (speedup 1.0000x reference)
#include <cuda_runtime.h>
#include <math.h>

#define N_ROWS 16384
#define D_DIM  2048
#define E_DIM  64
#define BM     64
#define KB     32
#define XPAD   36          // padded row stride for x tile (conflict-free, float4-aligned)
#define THREADS 128

// smem: union of (x tile 64x36 = 2304 floats) + (w tile 32x64 = 2048 floats) = 4352 floats
//       and epilogue logits buffer 64x68 = 4352 floats.
__global__ __launch_bounds__(THREADS, 8)
void router_kernel(const float* __restrict__ x,
                   const float* __restrict__ W,
                   const float* __restrict__ bias,
                   float* __restrict__ out_mask,
                   float* __restrict__ out_idx,
                   int write_idx)
{
    __shared__ float smem[4352];
    float* sx = smem;          // [BM][XPAD]
    float* sw = smem + BM * XPAD;  // [KB][E_DIM]

    const int tid = threadIdx.x;
    const int eg  = tid & 7;        // expert group: 8 experts each
    const int rg  = tid >> 3;       // 16 row groups
    const int rbase = rg * 4;       // 4 rows per thread
    const int row0 = blockIdx.x * BM;

    float acc[4][8];
#pragma unroll
    for (int i = 0; i < 4; i++)
#pragma unroll
        for (int j = 0; j < 8; j++) acc[i][j] = 0.0f;

    for (int k0 = 0; k0 < D_DIM; k0 += KB) {
        // load x tile: BM x KB = 512 float4, 4 per thread
#pragma unroll
        for (int i = tid; i < BM * (KB / 4); i += THREADS) {
            int r  = i >> 3;       // KB/4 = 8 float4 per row
            int c4 = i & 7;
            float4 v = *(const float4*)(x + (size_t)(row0 + r) * D_DIM + k0 + c4 * 4);
            *(float4*)(sx + r * XPAD + c4 * 4) = v;
        }
        // load W tile: KB x E = 512 float4, 4 per thread
#pragma unroll
        for (int i = tid; i < KB * (E_DIM / 4); i += THREADS) {
            int kk = i >> 4;       // E/4 = 16 float4 per row
            int e4 = i & 15;
            float4 v = *(const float4*)(W + (size_t)(k0 + kk) * E_DIM + e4 * 4);
            *(float4*)(sw + kk * E_DIM + e4 * 4) = v;
        }
        __syncthreads();

#pragma unroll 4
        for (int kk = 0; kk < KB; kk++) {
            float4 w0 = *(float4*)(sw + kk * E_DIM + eg * 8);
            float4 w1 = *(float4*)(sw + kk * E_DIM + eg * 8 + 4);
            float wv[8] = {w0.x, w0.y, w0.z, w0.w, w1.x, w1.y, w1.z, w1.w};
#pragma unroll
            for (int i = 0; i < 4; i++) {
                float xv = sx[(rbase + i) * XPAD + kk];
#pragma unroll
                for (int j = 0; j < 8; j++)
                    acc[i][j] = fmaf(xv, wv[j], acc[i][j]);
            }
        }
        __syncthreads();
    }

    // add bias, write logits to smem (reuse smem as [BM][68])
    float bv[8];
#pragma unroll
    for (int j = 0; j < 8; j++) bv[j] = bias[eg * 8 + j];

    float* slog = smem;
#pragma unroll
    for (int i = 0; i < 4; i++)
#pragma unroll
        for (int j = 0; j < 8; j++)
            slog[(rbase + i) * 68 + eg * 8 + j] = acc[i][j] + bv[j];
    __syncthreads();

    // epilogue: each warp handles 16 rows; softmax + top-2 + sparse mask
    const int wid  = tid >> 5;
    const int lane = tid & 31;
    const float NEG = -1e30f;

    for (int rr = 0; rr < 16; rr++) {
        int r = wid * 16 + rr;
        float v0 = slog[r * 68 + lane];
        float v1 = slog[r * 68 + lane + 32];

        // top-1 (tie-break: smaller index)
        float tv; int ti;
        if (v0 >= v1) { tv = v0; ti = lane; } else { tv = v1; ti = lane + 32; }
#pragma unroll
        for (int off = 16; off; off >>= 1) {
            float ov = __shfl_xor_sync(0xffffffffu, tv, off);
            int   oi = __shfl_xor_sync(0xffffffffu, ti, off);
            if (ov > tv || (ov == tv && oi < ti)) { tv = ov; ti = oi; }
        }
        float m = tv; int i1 = ti;

        // top-2: mask out i1
        float u0 = (lane == i1)        ? NEG : v0;
        float u1 = ((lane + 32) == i1) ? NEG : v1;
        if (u0 >= u1) { tv = u0; ti = lane; } else { tv = u1; ti = lane + 32; }
#pragma unroll
        for (int off = 16; off; off >>= 1) {
            float ov = __shfl_xor_sync(0xffffffffu, tv, off);
            int   oi = __shfl_xor_sync(0xffffffffu, ti, off);
            if (ov > tv || (ov == tv && oi < ti)) { tv = ov; ti = oi; }
        }
        float m2 = tv; int i2 = ti;

        // softmax denominator over all 64
        float s = expf(v0 - m) + expf(v1 - m);
#pragma unroll
        for (int off = 16; off; off >>= 1)
            s += __shfl_xor_sync(0xffffffffu, s, off);

        float g1 = 1.0f / s;          // exp(m - m)/s
        float g2 = expf(m2 - m) / s;

        float o0 = (lane == i1)        ? g1 : ((lane == i2)        ? g2 : 0.0f);
        float o1 = ((lane + 32) == i1) ? g1 : (((lane + 32) == i2) ? g2 : 0.0f);

        size_t ro = (size_t)(row0 + r) * E_DIM;
        out_mask[ro + lane]      = o0;
        out_mask[ro + lane + 32] = o1;
        if (write_idx && lane == 0) {
            out_idx[(size_t)(row0 + r) * 2]     = (float)i1;
            out_idx[(size_t)(row0 + r) * 2 + 1] = (float)i2;
        }
    }
}

extern "C" void kernel_launch(void* const* d_in, const int* in_sizes, int n_in,
                              void* d_out, int out_size) {
    const float* x = (const float*)d_in[0];
    const float* W = (const float*)d_in[1];
    const float* b = (const float*)d_in[2];
    float* out     = (float*)d_out;
    float* out_idx = out + (size_t)N_ROWS * E_DIM;
    int write_idx  = (out_size >= N_ROWS * (E_DIM + 2)) ? 1 : 0;

    router_kernel<<<N_ROWS / BM, THREADS>>>(x, W, b, out, out_idx, write_idx);
}